// round 14
// baseline (speedup 1.0000x reference)
#include <cuda_runtime.h>
#include <math.h>

// ---------------------------------------------------------------------------
// TrLaplacianDP: out = embs + noise, where noise[0:300] are the first 300
// accepted samples of a truncated-Laplacian rejection scan over (sgn, u).
//
// R14 (= R13 re-run; previous round failed on a container-init infra flake,
// "system not yet initialized" during harness CUDA init, before any kernel
// code executed).
//
// Single-kernel flag design with a SINGLE-SHOT scan: 256 threads x 16
// samples = 4096 samples in one round (expected accepts 473 >= 300;
// z=-8.5 against failure, chunked fallback loop retained). All 8 cold
// LDG.128 per thread issue up front -> one latency exposure instead of
// three serialized chunk rounds. Log-free mask (|r|<=A <=> u>=1-2/sqrt300),
// lazy logf only for stored values, exact log path in the boundary band.
// ---------------------------------------------------------------------------

#define EMBS_DIM 300
#define BLK      256
#define GRID     4800
#define IT       8
#define STRIDE   (GRID * BLK)        // 1228800 = 75 * 16384
#define SPT      16                  // samples per thread in the scan
#define NCHUNK   (BLK * SPT)         // 4096 samples per scan round

__device__ __align__(16) float g_noise[304];   // 75 float4 + pad
__device__ int g_flag = 0;    // 0 -> noise not ready; 1 -> ready
__device__ int g_done = 0;    // completed-block counter (replay reset)

__device__ __forceinline__ float sign_of(float x) {
    return (x > 0.0f) ? 1.0f : ((x < 0.0f) ? -1.0f : 0.0f);
}

// ---------------------------------------------------------------------------
// Noise scan (one 256-thread block). Thread t owns samples
// [base + t*16, base + t*16 + 16) -> thread order == sample order.
// ---------------------------------------------------------------------------
__device__ void scan_noise(const float* __restrict__ sgn,
                           const float* __restrict__ u, int n) {
    const double SCALE_D = 2.0 * 0.005 * sqrt(300.0) / 1.0;
    const float  SCALE_F = (float)SCALE_D;
    const float  A_F     = (float)(-SCALE_D * log(1.0 - 2.0 * 1.0 / sqrt(300.0)));
    const float  U_THR   = (float)(1.0 - 2.0 / sqrt(300.0));   // exp(-A/SCALE)
    const float  BAND    = 2e-5f;

    __shared__ int s_wsum[8];
    __shared__ int s_carry, s_total;

    const int tid  = threadIdx.x;
    const int lane = tid & 31;
    const int wid  = tid >> 5;         // 8 warps

    for (int i = tid; i < 304; i += BLK) g_noise[i] = 0.0f;
    if (tid == 0) s_carry = 0;
    __syncthreads();

    for (int base = 0; base < n; base += NCHUNK) {
        const int i0 = base + tid * SPT;
        float sv[SPT], uv[SPT];

        if (i0 + SPT - 1 < n) {
            // 8 independent LDG.128 — single cold-latency exposure.
            #pragma unroll
            for (int q = 0; q < SPT / 4; ++q) {
                const float4 s4 = *reinterpret_cast<const float4*>(sgn + i0 + 4 * q);
                const float4 u4 = *reinterpret_cast<const float4*>(u   + i0 + 4 * q);
                sv[4*q+0]=s4.x; sv[4*q+1]=s4.y; sv[4*q+2]=s4.z; sv[4*q+3]=s4.w;
                uv[4*q+0]=u4.x; uv[4*q+1]=u4.y; uv[4*q+2]=u4.z; uv[4*q+3]=u4.w;
            }
        } else {
            #pragma unroll
            for (int j = 0; j < SPT; ++j) {
                const int i = i0 + j;
                sv[j] = (i < n) ? sgn[i] : 0.0f;
                uv[j] = (i < n) ? u[i]   : 0.0f;   // u=0 -> fast reject
            }
        }

        bool  m[SPT], rdone[SPT];
        float rv[SPT];
        int cnt = 0;
        #pragma unroll
        for (int j = 0; j < SPT; ++j) {
            rdone[j] = false; rv[j] = 0.0f;
            if (fabsf(uv[j] - U_THR) < BAND || sv[j] == 0.0f) {
                // Exact path (rare): same semantics as passing kernels.
                const float s = sign_of(sv[j]);
                float r = (-SCALE_F * s) * logf(uv[j]);
                if (fabsf(fabsf(r) - A_F) < 1e-4f)
                    r = (-SCALE_F * s) * (float)log((double)uv[j]);
                m[j] = (uv[j] > 0.0f) && (r >= -A_F) && (r <= A_F);
                rv[j] = r; rdone[j] = true;
            } else {
                m[j] = (uv[j] >= U_THR);          // log-free mask
            }
            cnt += m[j] ? 1 : 0;
        }

        // Warp inclusive scan of per-thread counts, then 8-warp block scan.
        int incl = cnt;
        #pragma unroll
        for (int o = 1; o < 32; o <<= 1) {
            const int v = __shfl_up_sync(0xffffffffu, incl, o);
            if (lane >= o) incl += v;
        }
        if (lane == 31) s_wsum[wid] = incl;
        __syncthreads();

        if (wid == 0 && lane < 8) {
            const int v = s_wsum[lane];
            int iv = v;
            #pragma unroll
            for (int o = 1; o < 8; o <<= 1) {
                const int x = __shfl_up_sync(0x000000ffu, iv, o);
                if (lane >= o) iv += x;
            }
            s_wsum[lane] = iv - v;
            if (lane == 7) s_total = iv;
        }
        __syncthreads();

        int pos = s_carry + s_wsum[wid] + (incl - cnt);
        #pragma unroll
        for (int j = 0; j < SPT; ++j) {
            if (m[j]) {
                if (pos < EMBS_DIM) {
                    float r = rv[j];
                    if (!rdone[j])     // lazy logf: stored values only
                        r = (-SCALE_F * sign_of(sv[j])) * logf(uv[j]);
                    g_noise[pos] = r;
                }
                ++pos;
            }
        }
        __syncthreads();
        if (tid == 0) s_carry += s_total;
        __syncthreads();
        if (s_carry >= EMBS_DIM) break;          // uniform; 1 round typical
    }
}

// ---------------------------------------------------------------------------
// Fused kernel (exact shape): block 0 scans + publishes; consumers prefetch
// embs, poll the flag, add, store. Last finishing block resets flag state.
// ---------------------------------------------------------------------------
__global__ void __launch_bounds__(BLK) fused_kernel(
        const float* __restrict__ embs,
        const float* __restrict__ sgn,
        const float* __restrict__ u,
        float* __restrict__ out, int nsamp) {
    const float4* __restrict__ in4  = reinterpret_cast<const float4*>(embs);
    float4* __restrict__       out4 = reinterpret_cast<float4*>(out);

    const int tid = threadIdx.x;
    const int v0  = blockIdx.x * BLK + tid;

    if (blockIdx.x == 0) {
        // ---- Producer block: scan, release-publish, then own add slice. ----
        scan_noise(sgn, u, nsamp);
        __threadfence();
        __syncthreads();
        if (tid == 0) atomicExch(&g_flag, 1);

        const float4 nz = reinterpret_cast<const float4*>(g_noise)[v0 % 75];
        #pragma unroll
        for (int k = 0; k < IT; ++k) {
            const int vi = v0 + k * STRIDE;
            float4 t = __ldcs(&in4[vi]);
            t.x += nz.x; t.y += nz.y; t.z += nz.z; t.w += nz.w;
            __stcs(&out4[vi], t);
        }
    } else {
        // ---- Consumers: prefetch embs (independent of noise). ----
        float4 e[IT];
        #pragma unroll
        for (int k = 0; k < IT; ++k)
            e[k] = __ldcs(&in4[v0 + k * STRIDE]);

        // Poll-before-sleep (one thread; plain L2 load, no atomic traffic).
        if (tid == 0) {
            while (__ldcg(&g_flag) == 0) __nanosleep(64);
        }
        __syncthreads();
        __threadfence();                 // order g_noise reads after flag

        const float4 nz = reinterpret_cast<const float4*>(g_noise)[v0 % 75];
        #pragma unroll
        for (int k = 0; k < IT; ++k) {
            float4 t = e[k];
            t.x += nz.x; t.y += nz.y; t.z += nz.z; t.w += nz.w;
            __stcs(&out4[v0 + k * STRIDE], t);
        }
    }

    // ---- Replay-reset protocol: last finishing block clears state. ----
    __syncthreads();
    if (tid == 0) {
        const int prev = atomicAdd(&g_done, 1);
        if (prev == (int)gridDim.x - 1) {
            g_done = 0;
            atomicExch(&g_flag, 0);
            __threadfence();
        }
    }
}

// ---------------------------------------------------------------------------
// Fallback for non-exact shapes: two-kernel structure (scan, then add).
// ---------------------------------------------------------------------------
__global__ void __launch_bounds__(256) noise_kernel(const float* __restrict__ sgn,
                                                    const float* __restrict__ u,
                                                    int n) {
    scan_noise(sgn, u, n);
}

__global__ void __launch_bounds__(256) add_general_kernel(
        const float* __restrict__ embs, float* __restrict__ out,
        int n4, int n) {
    const float4* __restrict__ in4  = reinterpret_cast<const float4*>(embs);
    float4* __restrict__       out4 = reinterpret_cast<float4*>(out);

    const int stride = gridDim.x * blockDim.x;       // multiple of 75
    const int v0     = blockIdx.x * blockDim.x + threadIdx.x;
    const float4 nz  = reinterpret_cast<const float4*>(g_noise)[v0 % 75];

    for (int v = v0; v < n4; v += 8 * stride) {
        #pragma unroll
        for (int k = 0; k < 8; ++k) {
            const int vi = v + k * stride;
            if (vi < n4) {
                float4 t = __ldcs(&in4[vi]);
                t.x += nz.x; t.y += nz.y; t.z += nz.z; t.w += nz.w;
                __stcs(&out4[vi], t);
            }
        }
    }
    const int tail_start = n4 * 4;
    for (int i = tail_start + v0; i < n; i += stride)
        out[i] = embs[i] + g_noise[i % EMBS_DIM];
}

// ---------------------------------------------------------------------------
extern "C" void kernel_launch(void* const* d_in, const int* in_sizes, int n_in,
                              void* d_out, int out_size) {
    const float* embs = (const float*)d_in[0];
    const float* sgn  = (const float*)d_in[1];
    const float* u    = (const float*)d_in[2];
    float* out        = (float*)d_out;

    const int nsamp = in_sizes[1];
    const int n  = out_size;
    const int n4 = n / 4;

    if (n == n4 * 4 && n4 == GRID * BLK * IT) {
        fused_kernel<<<GRID, BLK>>>(embs, sgn, u, out, nsamp);
    } else {
        noise_kernel<<<1, 256>>>(sgn, u, nsamp);
        int grid = (n4 + 256 * 8 - 1) / (256 * 8);
        grid = ((grid + 74) / 75) * 75;             // stride % 75 == 0
        if (grid < 75) grid = 75;
        add_general_kernel<<<grid, 256>>>(embs, out, n4, n);
    }
}

// round 15
// speedup vs baseline: 1.0750x; 1.0750x over previous
#include <cuda_runtime.h>
#include <math.h>

// ---------------------------------------------------------------------------
// TrLaplacianDP: out = embs + noise, where noise[0:300] are the first 300
// accepted samples of a truncated-Laplacian rejection scan over (sgn, u).
//
// R15: R14's single-shot scan (256 thr x 16 samples, one round) with the
// REGISTER FOOTPRINT stripped: mask kept as a 16-bit bitmask, exact-band
// values recomputed at store time (identical arithmetic -> identical
// results), and __launch_bounds__(256,5) caps regs at ~51 so the streaming
// path keeps the proven ~50% occupancy / ~74% DRAM shape. Any spill hits
// only block 0's scan.
// ---------------------------------------------------------------------------

#define EMBS_DIM 300
#define BLK      256
#define GRID     4800
#define IT       8
#define STRIDE   (GRID * BLK)        // 1228800 = 75 * 16384
#define SPT      16                  // samples per thread in the scan
#define NCHUNK   (BLK * SPT)         // 4096 samples per scan round

__device__ __align__(16) float g_noise[304];   // 75 float4 + pad
__device__ int g_flag = 0;    // 0 -> noise not ready; 1 -> ready
__device__ int g_done = 0;    // completed-block counter (replay reset)

__device__ __forceinline__ float sign_of(float x) {
    return (x > 0.0f) ? 1.0f : ((x < 0.0f) ? -1.0f : 0.0f);
}

// Exact r computation (same semantics as all passing kernels): fp32 logf,
// with double-precision recompute inside the 1e-4 band around +-A.
__device__ __forceinline__ float compute_r_exact(float sv, float uv,
                                                 float SCALE_F, float A_F) {
    const float s = sign_of(sv);
    float r = (-SCALE_F * s) * logf(uv);
    if (fabsf(fabsf(r) - A_F) < 1e-4f)
        r = (-SCALE_F * s) * (float)log((double)uv);
    return r;
}

// ---------------------------------------------------------------------------
// Noise scan (one 256-thread block). Thread t owns samples
// [base + t*16, base + t*16 + 16) -> thread order == sample order.
// Live state across barriers: sv[16], uv[16], one bitmask.
// ---------------------------------------------------------------------------
__device__ void scan_noise(const float* __restrict__ sgn,
                           const float* __restrict__ u, int n) {
    const double SCALE_D = 2.0 * 0.005 * sqrt(300.0) / 1.0;
    const float  SCALE_F = (float)SCALE_D;
    const float  A_F     = (float)(-SCALE_D * log(1.0 - 2.0 * 1.0 / sqrt(300.0)));
    const float  U_THR   = (float)(1.0 - 2.0 / sqrt(300.0));   // exp(-A/SCALE)
    const float  BAND    = 2e-5f;

    __shared__ int s_wsum[8];
    __shared__ int s_carry, s_total;

    const int tid  = threadIdx.x;
    const int lane = tid & 31;
    const int wid  = tid >> 5;         // 8 warps

    for (int i = tid; i < 304; i += BLK) g_noise[i] = 0.0f;
    if (tid == 0) s_carry = 0;
    __syncthreads();

    for (int base = 0; base < n; base += NCHUNK) {
        const int i0 = base + tid * SPT;
        float sv[SPT], uv[SPT];

        if (i0 + SPT - 1 < n) {
            // 8 independent LDG.128 — single cold-latency exposure.
            #pragma unroll
            for (int q = 0; q < SPT / 4; ++q) {
                const float4 s4 = *reinterpret_cast<const float4*>(sgn + i0 + 4 * q);
                const float4 u4 = *reinterpret_cast<const float4*>(u   + i0 + 4 * q);
                sv[4*q+0]=s4.x; sv[4*q+1]=s4.y; sv[4*q+2]=s4.z; sv[4*q+3]=s4.w;
                uv[4*q+0]=u4.x; uv[4*q+1]=u4.y; uv[4*q+2]=u4.z; uv[4*q+3]=u4.w;
            }
        } else {
            #pragma unroll
            for (int j = 0; j < SPT; ++j) {
                const int i = i0 + j;
                sv[j] = (i < n) ? sgn[i] : 0.0f;
                uv[j] = (i < n) ? u[i]   : 0.0f;   // u=0 -> fast reject
            }
        }

        // Mask as a bitmask; no per-sample r storage.
        unsigned mbits = 0;
        #pragma unroll
        for (int j = 0; j < SPT; ++j) {
            bool mj;
            if (fabsf(uv[j] - U_THR) < BAND || sv[j] == 0.0f) {
                // Exact decision path (rare).
                const float r = compute_r_exact(sv[j], uv[j], SCALE_F, A_F);
                mj = (uv[j] > 0.0f) && (r >= -A_F) && (r <= A_F);
            } else {
                mj = (uv[j] >= U_THR);            // log-free mask
            }
            mbits |= (unsigned)mj << j;
        }
        const int cnt = __popc(mbits);

        // Warp inclusive scan of per-thread counts, then 8-warp block scan.
        int incl = cnt;
        #pragma unroll
        for (int o = 1; o < 32; o <<= 1) {
            const int v = __shfl_up_sync(0xffffffffu, incl, o);
            if (lane >= o) incl += v;
        }
        if (lane == 31) s_wsum[wid] = incl;
        __syncthreads();

        if (wid == 0 && lane < 8) {
            const int v = s_wsum[lane];
            int iv = v;
            #pragma unroll
            for (int o = 1; o < 8; o <<= 1) {
                const int x = __shfl_up_sync(0x000000ffu, iv, o);
                if (lane >= o) iv += x;
            }
            s_wsum[lane] = iv - v;
            if (lane == 7) s_total = iv;
        }
        __syncthreads();

        // Store phase: recompute r (incl. exact-band handling) only for
        // accepted samples that land at pos < 300 (~300 total).
        int pos = s_carry + s_wsum[wid] + (incl - cnt);
        if (pos < EMBS_DIM && mbits) {
            #pragma unroll
            for (int j = 0; j < SPT; ++j) {
                if ((mbits >> j) & 1u) {
                    if (pos < EMBS_DIM)
                        g_noise[pos] = compute_r_exact(sv[j], uv[j], SCALE_F, A_F);
                    ++pos;
                }
            }
        }
        __syncthreads();
        if (tid == 0) s_carry += s_total;
        __syncthreads();
        if (s_carry >= EMBS_DIM) break;          // uniform; 1 round typical
    }
}

// ---------------------------------------------------------------------------
// Fused kernel (exact shape): block 0 scans + publishes; consumers prefetch
// embs, poll the flag, add, store. Last finishing block resets flag state.
// __launch_bounds__(256,5) caps regs (~51) to protect streaming occupancy.
// ---------------------------------------------------------------------------
__global__ void __launch_bounds__(BLK, 5) fused_kernel(
        const float* __restrict__ embs,
        const float* __restrict__ sgn,
        const float* __restrict__ u,
        float* __restrict__ out, int nsamp) {
    const float4* __restrict__ in4  = reinterpret_cast<const float4*>(embs);
    float4* __restrict__       out4 = reinterpret_cast<float4*>(out);

    const int tid = threadIdx.x;
    const int v0  = blockIdx.x * BLK + tid;

    if (blockIdx.x == 0) {
        // ---- Producer block: scan, release-publish, then own add slice. ----
        scan_noise(sgn, u, nsamp);
        __threadfence();
        __syncthreads();
        if (tid == 0) atomicExch(&g_flag, 1);

        const float4 nz = reinterpret_cast<const float4*>(g_noise)[v0 % 75];
        #pragma unroll
        for (int k = 0; k < IT; ++k) {
            const int vi = v0 + k * STRIDE;
            float4 t = __ldcs(&in4[vi]);
            t.x += nz.x; t.y += nz.y; t.z += nz.z; t.w += nz.w;
            __stcs(&out4[vi], t);
        }
    } else {
        // ---- Consumers: prefetch embs (independent of noise). ----
        float4 e[IT];
        #pragma unroll
        for (int k = 0; k < IT; ++k)
            e[k] = __ldcs(&in4[v0 + k * STRIDE]);

        // Poll-before-sleep (one thread; plain L2 load, no atomic traffic).
        if (tid == 0) {
            while (__ldcg(&g_flag) == 0) __nanosleep(64);
        }
        __syncthreads();
        __threadfence();                 // order g_noise reads after flag

        const float4 nz = reinterpret_cast<const float4*>(g_noise)[v0 % 75];
        #pragma unroll
        for (int k = 0; k < IT; ++k) {
            float4 t = e[k];
            t.x += nz.x; t.y += nz.y; t.z += nz.z; t.w += nz.w;
            __stcs(&out4[v0 + k * STRIDE], t);
        }
    }

    // ---- Replay-reset protocol: last finishing block clears state. ----
    __syncthreads();
    if (tid == 0) {
        const int prev = atomicAdd(&g_done, 1);
        if (prev == (int)gridDim.x - 1) {
            g_done = 0;
            atomicExch(&g_flag, 0);
            __threadfence();
        }
    }
}

// ---------------------------------------------------------------------------
// Fallback for non-exact shapes: two-kernel structure (scan, then add).
// ---------------------------------------------------------------------------
__global__ void __launch_bounds__(256) noise_kernel(const float* __restrict__ sgn,
                                                    const float* __restrict__ u,
                                                    int n) {
    scan_noise(sgn, u, n);
}

__global__ void __launch_bounds__(256) add_general_kernel(
        const float* __restrict__ embs, float* __restrict__ out,
        int n4, int n) {
    const float4* __restrict__ in4  = reinterpret_cast<const float4*>(embs);
    float4* __restrict__       out4 = reinterpret_cast<float4*>(out);

    const int stride = gridDim.x * blockDim.x;       // multiple of 75
    const int v0     = blockIdx.x * blockDim.x + threadIdx.x;
    const float4 nz  = reinterpret_cast<const float4*>(g_noise)[v0 % 75];

    for (int v = v0; v < n4; v += 8 * stride) {
        #pragma unroll
        for (int k = 0; k < 8; ++k) {
            const int vi = v + k * stride;
            if (vi < n4) {
                float4 t = __ldcs(&in4[vi]);
                t.x += nz.x; t.y += nz.y; t.z += nz.z; t.w += nz.w;
                __stcs(&out4[vi], t);
            }
        }
    }
    const int tail_start = n4 * 4;
    for (int i = tail_start + v0; i < n; i += stride)
        out[i] = embs[i] + g_noise[i % EMBS_DIM];
}

// ---------------------------------------------------------------------------
extern "C" void kernel_launch(void* const* d_in, const int* in_sizes, int n_in,
                              void* d_out, int out_size) {
    const float* embs = (const float*)d_in[0];
    const float* sgn  = (const float*)d_in[1];
    const float* u    = (const float*)d_in[2];
    float* out        = (float*)d_out;

    const int nsamp = in_sizes[1];
    const int n  = out_size;
    const int n4 = n / 4;

    if (n == n4 * 4 && n4 == GRID * BLK * IT) {
        fused_kernel<<<GRID, BLK>>>(embs, sgn, u, out, nsamp);
    } else {
        noise_kernel<<<1, 256>>>(sgn, u, nsamp);
        int grid = (n4 + 256 * 8 - 1) / (256 * 8);
        grid = ((grid + 74) / 75) * 75;             // stride % 75 == 0
        if (grid < 75) grid = 75;
        add_general_kernel<<<grid, 256>>>(embs, out, n4, n);
    }
}

// round 16
// speedup vs baseline: 1.1360x; 1.0567x over previous
#include <cuda_runtime.h>
#include <math.h>

// ---------------------------------------------------------------------------
// TrLaplacianDP: out = embs + noise, where noise[0:300] are the first 300
// accepted samples of a truncated-Laplacian rejection scan over (sgn, u).
//
// R16: the proven R9 two-kernel PDL structure (trigger at entry of the
// noise kernel; add kernel prefetches embs before gridDepSync; 4800x256
// exact-fit stream at ~74% DRAM), with the noise kernel upgraded to the
// single-shot scan: 256 threads x 16 samples = 4096 samples in ONE round
// (expected accepts 473 >= 300; chunked fallback retained). Mask held as a
// bitmask; r recomputed at store time (identical arithmetic). Log-free
// mask |r|<=A <=> u >= 1-2/sqrt(300); exact log path in the 2e-5 band.
// ---------------------------------------------------------------------------

#define EMBS_DIM 300
#define T_N      256
#define SPT      16
#define NCHUNK   (T_N * SPT)          // 4096 samples per scan round

#define ADD_GRID  4800
#define ADD_BLK   256
#define ADD_IT    8
#define ADD_STRIDE (ADD_GRID * ADD_BLK)   // 1228800 = 75 * 16384

__device__ __align__(16) float g_noise[304];   // 75 float4 + pad

__device__ __forceinline__ float sign_of(float x) {
    return (x > 0.0f) ? 1.0f : ((x < 0.0f) ? -1.0f : 0.0f);
}

// Exact r computation (same semantics as all passing kernels): fp32 logf,
// with double-precision recompute inside the 1e-4 band around +-A.
__device__ __forceinline__ float compute_r_exact(float sv, float uv,
                                                 float SCALE_F, float A_F) {
    const float s = sign_of(sv);
    float r = (-SCALE_F * s) * logf(uv);
    if (fabsf(fabsf(r) - A_F) < 1e-4f)
        r = (-SCALE_F * s) * (float)log((double)uv);
    return r;
}

// ---------------------------------------------------------------------------
// Kernel N (single 256-thread block): PDL trigger at entry, then the
// single-shot ordered rejection scan. Thread t owns samples
// [base + t*16, base + t*16 + 16) -> thread order == sample order.
// ---------------------------------------------------------------------------
__global__ void __launch_bounds__(T_N) noise_kernel(const float* __restrict__ sgn,
                                                    const float* __restrict__ u,
                                                    int n) {
    // Release the dependent add grid IMMEDIATELY: its launch+prefetch runs
    // concurrently with this scan. Ordering of g_noise is enforced by the
    // secondary's cudaGridDependencySynchronize() (waits for completion).
    cudaTriggerProgrammaticLaunchCompletion();

    const double SCALE_D = 2.0 * 0.005 * sqrt(300.0) / 1.0;
    const float  SCALE_F = (float)SCALE_D;
    const float  A_F     = (float)(-SCALE_D * log(1.0 - 2.0 * 1.0 / sqrt(300.0)));
    const float  U_THR   = (float)(1.0 - 2.0 / sqrt(300.0));   // exp(-A/SCALE)
    const float  BAND    = 2e-5f;

    __shared__ int s_wsum[8];
    __shared__ int s_carry, s_total;

    const int tid  = threadIdx.x;
    const int lane = tid & 31;
    const int wid  = tid >> 5;         // 8 warps

    for (int i = tid; i < 304; i += T_N) g_noise[i] = 0.0f;
    if (tid == 0) s_carry = 0;
    __syncthreads();

    for (int base = 0; base < n; base += NCHUNK) {
        const int i0 = base + tid * SPT;
        float sv[SPT], uv[SPT];

        if (i0 + SPT - 1 < n) {
            // 8 independent LDG.128 — single cold-latency exposure.
            #pragma unroll
            for (int q = 0; q < SPT / 4; ++q) {
                const float4 s4 = *reinterpret_cast<const float4*>(sgn + i0 + 4 * q);
                const float4 u4 = *reinterpret_cast<const float4*>(u   + i0 + 4 * q);
                sv[4*q+0]=s4.x; sv[4*q+1]=s4.y; sv[4*q+2]=s4.z; sv[4*q+3]=s4.w;
                uv[4*q+0]=u4.x; uv[4*q+1]=u4.y; uv[4*q+2]=u4.z; uv[4*q+3]=u4.w;
            }
        } else {
            #pragma unroll
            for (int j = 0; j < SPT; ++j) {
                const int i = i0 + j;
                sv[j] = (i < n) ? sgn[i] : 0.0f;
                uv[j] = (i < n) ? u[i]   : 0.0f;   // u=0 -> fast reject
            }
        }

        // Mask as a bitmask; no per-sample r storage.
        unsigned mbits = 0;
        #pragma unroll
        for (int j = 0; j < SPT; ++j) {
            bool mj;
            if (fabsf(uv[j] - U_THR) < BAND || sv[j] == 0.0f) {
                const float r = compute_r_exact(sv[j], uv[j], SCALE_F, A_F);
                mj = (uv[j] > 0.0f) && (r >= -A_F) && (r <= A_F);
            } else {
                mj = (uv[j] >= U_THR);            // log-free mask
            }
            mbits |= (unsigned)mj << j;
        }
        const int cnt = __popc(mbits);

        // Warp inclusive scan of per-thread counts, then 8-warp block scan.
        int incl = cnt;
        #pragma unroll
        for (int o = 1; o < 32; o <<= 1) {
            const int v = __shfl_up_sync(0xffffffffu, incl, o);
            if (lane >= o) incl += v;
        }
        if (lane == 31) s_wsum[wid] = incl;
        __syncthreads();

        if (wid == 0 && lane < 8) {
            const int v = s_wsum[lane];
            int iv = v;
            #pragma unroll
            for (int o = 1; o < 8; o <<= 1) {
                const int x = __shfl_up_sync(0x000000ffu, iv, o);
                if (lane >= o) iv += x;
            }
            s_wsum[lane] = iv - v;
            if (lane == 7) s_total = iv;
        }
        __syncthreads();

        // Store phase: recompute r only for accepted samples at pos < 300.
        int pos = s_carry + s_wsum[wid] + (incl - cnt);
        if (pos < EMBS_DIM && mbits) {
            #pragma unroll
            for (int j = 0; j < SPT; ++j) {
                if ((mbits >> j) & 1u) {
                    if (pos < EMBS_DIM)
                        g_noise[pos] = compute_r_exact(sv[j], uv[j], SCALE_F, A_F);
                    ++pos;
                }
            }
        }
        __syncthreads();
        if (tid == 0) s_carry += s_total;
        __syncthreads();
        if (s_carry >= EMBS_DIM) break;          // uniform; 1 round typical
    }
}

// ---------------------------------------------------------------------------
// Kernel B (exact fit): prefetch embs BEFORE the PDL grid sync, then add.
// (Unchanged from R9: 44.4us @ 73.9% DRAM.)
// ---------------------------------------------------------------------------
__global__ void __launch_bounds__(ADD_BLK) add_exact_kernel(
        const float* __restrict__ embs, float* __restrict__ out) {
    const float4* __restrict__ in4  = reinterpret_cast<const float4*>(embs);
    float4* __restrict__       out4 = reinterpret_cast<float4*>(out);

    const int v0 = blockIdx.x * ADD_BLK + threadIdx.x;

    // ---- Pre-sync: everything independent of g_noise. ----
    const float4* nzp = &reinterpret_cast<const float4*>(g_noise)[v0 % 75];
    float4 e[ADD_IT];
    #pragma unroll
    for (int k = 0; k < ADD_IT; ++k)
        e[k] = __ldcs(&in4[v0 + k * ADD_STRIDE]);

    // ---- Wait for noise kernel completion (no-op without PDL). ----
    cudaGridDependencySynchronize();

    const float4 nz = *nzp;   // L2-broadcast LDG.128; loop-invariant

    #pragma unroll
    for (int k = 0; k < ADD_IT; ++k) {
        float4 t = e[k];
        t.x += nz.x; t.y += nz.y; t.z += nz.z; t.w += nz.w;
        __stcs(&out4[v0 + k * ADD_STRIDE], t);
    }
}

// ---------------------------------------------------------------------------
// Kernel B (general fallback): any shape. PDL-aware.
// ---------------------------------------------------------------------------
__global__ void __launch_bounds__(256) add_general_kernel(
        const float* __restrict__ embs, float* __restrict__ out,
        int n4, int n) {
    cudaGridDependencySynchronize();

    const float4* __restrict__ in4  = reinterpret_cast<const float4*>(embs);
    float4* __restrict__       out4 = reinterpret_cast<float4*>(out);

    const int stride = gridDim.x * blockDim.x;       // multiple of 75
    const int v0     = blockIdx.x * blockDim.x + threadIdx.x;
    const float4 nz  = reinterpret_cast<const float4*>(g_noise)[v0 % 75];

    for (int v = v0; v < n4; v += 8 * stride) {
        #pragma unroll
        for (int k = 0; k < 8; ++k) {
            const int vi = v + k * stride;
            if (vi < n4) {
                float4 t = __ldcs(&in4[vi]);
                t.x += nz.x; t.y += nz.y; t.z += nz.z; t.w += nz.w;
                __stcs(&out4[vi], t);
            }
        }
    }
    const int tail_start = n4 * 4;
    for (int i = tail_start + v0; i < n; i += stride)
        out[i] = embs[i] + g_noise[i % EMBS_DIM];
}

// ---------------------------------------------------------------------------
extern "C" void kernel_launch(void* const* d_in, const int* in_sizes, int n_in,
                              void* d_out, int out_size) {
    const float* embs = (const float*)d_in[0];
    const float* sgn  = (const float*)d_in[1];
    const float* u    = (const float*)d_in[2];
    float* out        = (float*)d_out;

    const int nsamp = in_sizes[1];
    noise_kernel<<<1, T_N>>>(sgn, u, nsamp);

    const int n  = out_size;
    const int n4 = n / 4;

    if (n == n4 * 4 && n4 == ADD_GRID * ADD_BLK * ADD_IT) {
        cudaLaunchConfig_t cfg = {};
        cfg.gridDim  = dim3(ADD_GRID, 1, 1);
        cfg.blockDim = dim3(ADD_BLK, 1, 1);
        cudaLaunchAttribute attr[1];
        attr[0].id = cudaLaunchAttributeProgrammaticStreamSerialization;
        attr[0].val.programmaticStreamSerializationAllowed = 1;
        cfg.attrs = attr;
        cfg.numAttrs = 1;
        cudaError_t e = cudaLaunchKernelEx(&cfg, add_exact_kernel, embs, out);
        if (e != cudaSuccess) {
            (void)cudaGetLastError();               // clear sticky error
            add_exact_kernel<<<ADD_GRID, ADD_BLK>>>(embs, out);
        }
    } else {
        int grid = (n4 + 256 * 8 - 1) / (256 * 8);
        grid = ((grid + 74) / 75) * 75;             // stride % 75 == 0
        if (grid < 75) grid = 75;
        add_general_kernel<<<grid, 256>>>(embs, out, n4, n);
    }
}